// round 2
// baseline (speedup 1.0000x reference)
#include <cuda_runtime.h>
#include <math.h>

#define B_   4
#define LQ_  2048
#define LK_  2048
#define XS_  1024
#define PD_  128

// Scratch for projected q/k/v (device globals: no allocation allowed)
__device__ float g_q[B_ * LQ_ * PD_];
__device__ float g_k[B_ * LK_ * PD_];
__device__ float g_v[B_ * LK_ * PD_];

// ---------------------------------------------------------------------------
// Projection GEMM: C[M=8192,128] = A[8192,1024] @ W[1024,128] + bias
// grid.x = M/128 (64), grid.y = {0:q, 1:k, 2:v}, 256 threads
// 128x128 tile, BK=8, 8x8 microtile per thread (cols split tx*4 and 64+tx*4
// for conflict-free smem reads and coalesced stores).
// ---------------------------------------------------------------------------
__global__ __launch_bounds__(256) void proj_kernel(
    const float* __restrict__ x, const float* __restrict__ y,
    const float* __restrict__ Wq, const float* __restrict__ bq,
    const float* __restrict__ Wk, const float* __restrict__ bk,
    const float* __restrict__ Wv, const float* __restrict__ bv)
{
    const float* A; const float* W; const float* bias; float* C;
    if (blockIdx.y == 0)      { A = x; W = Wq; bias = bq; C = g_q; }
    else if (blockIdx.y == 1) { A = y; W = Wk; bias = bk; C = g_k; }
    else                      { A = y; W = Wv; bias = bv; C = g_v; }

    __shared__ float As[8][128];   // [k][row]  (transposed A tile)
    __shared__ float Bs[8][128];   // [k][col]

    const int tid = threadIdx.x;
    const int ty = tid >> 4;       // 0..15 -> 8 rows each
    const int tx = tid & 15;       // 0..15 -> cols tx*4 and 64+tx*4
    const int row0 = blockIdx.x * 128;

    float acc[8][8];
    #pragma unroll
    for (int i = 0; i < 8; i++)
        #pragma unroll
        for (int j = 0; j < 8; j++) acc[i][j] = 0.0f;

    const int lr  = tid >> 1;         // A-tile row this thread loads
    const int lkc = (tid & 1) * 4;    // A-tile col group
    const int bkr = tid >> 5;         // W-tile row
    const int bcol = (tid & 31) * 4;  // W-tile col group

    for (int k0 = 0; k0 < 1024; k0 += 8) {
        float4 av = *(const float4*)(A + (size_t)(row0 + lr) * 1024 + k0 + lkc);
        float4 wv = *(const float4*)(W + (size_t)(k0 + bkr) * 128 + bcol);
        As[lkc + 0][lr] = av.x;
        As[lkc + 1][lr] = av.y;
        As[lkc + 2][lr] = av.z;
        As[lkc + 3][lr] = av.w;
        *(float4*)&Bs[bkr][bcol] = wv;
        __syncthreads();

        #pragma unroll
        for (int kk = 0; kk < 8; kk++) {
            float a[8], b[8];
            *(float4*)&a[0] = *(float4*)&As[kk][ty * 8];
            *(float4*)&a[4] = *(float4*)&As[kk][ty * 8 + 4];
            *(float4*)&b[0] = *(float4*)&Bs[kk][tx * 4];
            *(float4*)&b[4] = *(float4*)&Bs[kk][64 + tx * 4];
            #pragma unroll
            for (int i = 0; i < 8; i++)
                #pragma unroll
                for (int j = 0; j < 8; j++)
                    acc[i][j] = fmaf(a[i], b[j], acc[i][j]);
        }
        __syncthreads();
    }

    float bvals[8];
    *(float4*)&bvals[0] = *(const float4*)(bias + tx * 4);
    *(float4*)&bvals[4] = *(const float4*)(bias + 64 + tx * 4);

    #pragma unroll
    for (int i = 0; i < 8; i++) {
        const int row = row0 + ty * 8 + i;
        float4 o0 = make_float4(acc[i][0] + bvals[0], acc[i][1] + bvals[1],
                                acc[i][2] + bvals[2], acc[i][3] + bvals[3]);
        float4 o1 = make_float4(acc[i][4] + bvals[4], acc[i][5] + bvals[5],
                                acc[i][6] + bvals[6], acc[i][7] + bvals[7]);
        *(float4*)(C + (size_t)row * 128 + tx * 4) = o0;
        *(float4*)(C + (size_t)row * 128 + 64 + tx * 4) = o1;
    }
}

// ---------------------------------------------------------------------------
// Flash attention with post-softmax triu(k=1) mask:
//   online max/denominator over ALL keys, numerator only for k > q.
// grid = (LQ/64, B), 256 threads. Thread (ty,tx): S rows ty*4, S cols tx*4,
// O cols tx*4 and 64+tx*4.
// ---------------------------------------------------------------------------
#define BQ  64
#define BKT 64
// Pitch MUST be a multiple of 4 so float4 smem accesses stay 16B-aligned
// (pitch 65 caused the round-1 "misaligned address" trap). 68 = 4 mod 32
// banks, so consecutive d-rows still shift banks.
#define QK_PITCH 68
// smem (floats): Qs[128][68] | Ks[128][68] | Vs[64][128] | Ps[64][68]
#define SMF_Q 0
#define SMF_K (128 * QK_PITCH)
#define SMF_V (2 * 128 * QK_PITCH)
#define SMF_P (2 * 128 * QK_PITCH + 64 * 128)
#define SMEM_FLOATS (2 * 128 * QK_PITCH + 64 * 128 + 64 * QK_PITCH)
#define SMEM_BYTES (SMEM_FLOATS * 4)

__global__ __launch_bounds__(256) void attn_kernel(const int* __restrict__ maskp,
                                                   float* __restrict__ out)
{
    extern __shared__ float sm[];
    float* Qs = sm + SMF_Q;   // [d][r]  pitch 68
    float* Ks = sm + SMF_K;   // [d][j]  pitch 68
    float* Vs = sm + SMF_V;   // [j][d]  pitch 128
    float* Ps = sm + SMF_P;   // [r][j]  pitch 68

    const int b = blockIdx.y;
    const int qbase = blockIdx.x * BQ;
    const float* Qg = g_q + ((size_t)b * LQ_ + qbase) * PD_;
    const float* Kg = g_k + (size_t)b * LK_ * PD_;
    const float* Vg = g_v + (size_t)b * LK_ * PD_;

    const int tid = threadIdx.x;
    const int ty = tid >> 4, tx = tid & 15;
    const int r0 = ty * 4;
    const int c0 = tx * 4;
    const int msk = *maskp;

    // Load Q tile transposed: Qs[d][r]
    for (int idx = tid; idx < 64 * 32; idx += 256) {
        const int r = idx & 63, dg = idx >> 6;
        float4 qv = *(const float4*)(Qg + (size_t)r * PD_ + dg * 4);
        Qs[(dg * 4 + 0) * QK_PITCH + r] = qv.x;
        Qs[(dg * 4 + 1) * QK_PITCH + r] = qv.y;
        Qs[(dg * 4 + 2) * QK_PITCH + r] = qv.z;
        Qs[(dg * 4 + 3) * QK_PITCH + r] = qv.w;
    }

    float m_run[4], l_run[4], o[4][8];
    #pragma unroll
    for (int i = 0; i < 4; i++) {
        m_run[i] = -1e30f;
        l_run[i] = 0.0f;
        #pragma unroll
        for (int d = 0; d < 8; d++) o[i][d] = 0.0f;
    }

    const float SCALE = 0.0883883476483184f;  // 1/sqrt(128)

    for (int t = 0; t < LK_ / BKT; t++) {
        const int kbase = t * BKT;
        __syncthreads();  // prior tile's PV done before overwriting Ks/Vs/Ps

        // K tile transposed: Ks[d][j]
        for (int idx = tid; idx < 64 * 32; idx += 256) {
            const int j = idx & 63, dg = idx >> 6;
            float4 kv = *(const float4*)(Kg + (size_t)(kbase + j) * PD_ + dg * 4);
            Ks[(dg * 4 + 0) * QK_PITCH + j] = kv.x;
            Ks[(dg * 4 + 1) * QK_PITCH + j] = kv.y;
            Ks[(dg * 4 + 2) * QK_PITCH + j] = kv.z;
            Ks[(dg * 4 + 3) * QK_PITCH + j] = kv.w;
        }
        // V tile row-major: Vs[j][d]
        for (int idx = tid; idx < 64 * 32; idx += 256) {
            const int j = idx >> 5, dg = idx & 31;
            *(float4*)&Vs[j * 128 + dg * 4] =
                *(const float4*)(Vg + (size_t)(kbase + j) * PD_ + dg * 4);
        }
        __syncthreads();

        // S = Q @ K^T  (4x4 per thread)
        float s[4][4];
        #pragma unroll
        for (int i = 0; i < 4; i++)
            #pragma unroll
            for (int j = 0; j < 4; j++) s[i][j] = 0.0f;

        #pragma unroll 8
        for (int d = 0; d < 128; d++) {
            float4 aa = *(float4*)&Qs[d * QK_PITCH + r0];
            float4 bb = *(float4*)&Ks[d * QK_PITCH + c0];
            const float a4[4] = {aa.x, aa.y, aa.z, aa.w};
            const float b4[4] = {bb.x, bb.y, bb.z, bb.w};
            #pragma unroll
            for (int i = 0; i < 4; i++)
                #pragma unroll
                for (int j = 0; j < 4; j++)
                    s[i][j] = fmaf(a4[i], b4[j], s[i][j]);
        }
        #pragma unroll
        for (int i = 0; i < 4; i++)
            #pragma unroll
            for (int j = 0; j < 4; j++) s[i][j] *= SCALE;

        // Row max over the 64-wide tile (reduce across the 16 tx lanes)
        float tm[4];
        #pragma unroll
        for (int i = 0; i < 4; i++)
            tm[i] = fmaxf(fmaxf(s[i][0], s[i][1]), fmaxf(s[i][2], s[i][3]));
        #pragma unroll
        for (int off = 8; off >= 1; off >>= 1)
            #pragma unroll
            for (int i = 0; i < 4; i++)
                tm[i] = fmaxf(tm[i], __shfl_xor_sync(0xffffffffu, tm[i], off));

        float m_new[4], corr[4], lp[4];
        #pragma unroll
        for (int i = 0; i < 4; i++) {
            m_new[i] = fmaxf(m_run[i], tm[i]);
            corr[i] = __expf(m_run[i] - m_new[i]);
        }

        // exp, partial denominator (ALL keys), masked numerator to smem
        #pragma unroll
        for (int i = 0; i < 4; i++) {
            const int qidx = qbase + r0 + i;
            float ps = 0.0f;
            #pragma unroll
            for (int jj = 0; jj < 4; jj++) {
                const float e = __expf(s[i][jj] - m_new[i]);
                ps += e;
                const int kidx = kbase + c0 + jj;
                Ps[(r0 + i) * QK_PITCH + c0 + jj] =
                    (msk && (kidx <= qidx)) ? 0.0f : e;
            }
            lp[i] = ps;
        }
        #pragma unroll
        for (int off = 8; off >= 1; off >>= 1)
            #pragma unroll
            for (int i = 0; i < 4; i++)
                lp[i] += __shfl_xor_sync(0xffffffffu, lp[i], off);

        #pragma unroll
        for (int i = 0; i < 4; i++) {
            l_run[i] = l_run[i] * corr[i] + lp[i];
            m_run[i] = m_new[i];
            #pragma unroll
            for (int d = 0; d < 8; d++) o[i][d] *= corr[i];
        }
        __syncthreads();

        // O += P @ V
        #pragma unroll 2
        for (int j = 0; j < BKT; j++) {
            float4 v0 = *(float4*)&Vs[j * 128 + tx * 4];
            float4 v1 = *(float4*)&Vs[j * 128 + 64 + tx * 4];
            #pragma unroll
            for (int i = 0; i < 4; i++) {
                const float p = Ps[(r0 + i) * QK_PITCH + j];
                o[i][0] = fmaf(p, v0.x, o[i][0]);
                o[i][1] = fmaf(p, v0.y, o[i][1]);
                o[i][2] = fmaf(p, v0.z, o[i][2]);
                o[i][3] = fmaf(p, v0.w, o[i][3]);
                o[i][4] = fmaf(p, v1.x, o[i][4]);
                o[i][5] = fmaf(p, v1.y, o[i][5]);
                o[i][6] = fmaf(p, v1.z, o[i][6]);
                o[i][7] = fmaf(p, v1.w, o[i][7]);
            }
        }
    }

    // Epilogue: divide by full-softmax denominator, write out
    float* Og = out + ((size_t)b * LQ_ + qbase) * PD_;
    #pragma unroll
    for (int i = 0; i < 4; i++) {
        const float inv = 1.0f / l_run[i];
        float4 w0 = make_float4(o[i][0] * inv, o[i][1] * inv, o[i][2] * inv, o[i][3] * inv);
        float4 w1 = make_float4(o[i][4] * inv, o[i][5] * inv, o[i][6] * inv, o[i][7] * inv);
        *(float4*)(Og + (size_t)(r0 + i) * PD_ + tx * 4) = w0;
        *(float4*)(Og + (size_t)(r0 + i) * PD_ + 64 + tx * 4) = w1;
    }
}

// ---------------------------------------------------------------------------
extern "C" void kernel_launch(void* const* d_in, const int* in_sizes, int n_in,
                              void* d_out, int out_size)
{
    const float* x  = (const float*)d_in[0];
    const float* y  = (const float*)d_in[1];
    const float* Wq = (const float*)d_in[2];
    const float* bq = (const float*)d_in[3];
    const float* Wk = (const float*)d_in[4];
    const float* bk = (const float*)d_in[5];
    const float* Wv = (const float*)d_in[6];
    const float* bv = (const float*)d_in[7];
    const int* maskp = (const int*)d_in[8];
    float* out = (float*)d_out;

    (void)in_sizes; (void)n_in; (void)out_size;

    // Idempotent; needed for ~117 KB dynamic smem (> 48 KB default).
    cudaFuncSetAttribute(attn_kernel,
                         cudaFuncAttributeMaxDynamicSharedMemorySize, SMEM_BYTES);

    dim3 pg(64, 3);
    proj_kernel<<<pg, 256>>>(x, y, Wq, bq, Wk, bk, Wv, bv);

    dim3 ag(LQ_ / BQ, B_);
    attn_kernel<<<ag, 256, SMEM_BYTES>>>(maskp, out);
}

// round 3
// speedup vs baseline: 3.0476x; 3.0476x over previous
#include <cuda_runtime.h>
#include <cuda_pipeline.h>
#include <math.h>

#define B_   4
#define LQ_  2048
#define LK_  2048
#define XS_  1024
#define PD_  128

// Scratch for projected q/k/v (device globals: no allocation allowed).
// Values stored here are ALREADY rounded to TF32 (cvt.rna) so the attention
// kernel can cp.async them raw and the MMA truncation is lossless.
__device__ float g_q[B_ * LQ_ * PD_];
__device__ float g_k[B_ * LK_ * PD_];
__device__ float g_v[B_ * LK_ * PD_];

__device__ __forceinline__ float to_tf32(float x) {
    float r;
    asm("cvt.rna.tf32.f32 %0, %1;" : "=f"(r) : "f"(x));
    return r;
}

// D += A*B, m16n8k8 tf32. a: 4 regs, b: 2 regs, c: 4 fp32.
__device__ __forceinline__ void mma_tf32(float* c, const float* a, const float* b) {
    asm volatile(
        "mma.sync.aligned.m16n8k8.row.col.f32.tf32.tf32.f32 "
        "{%0,%1,%2,%3}, {%4,%5,%6,%7}, {%8,%9}, {%0,%1,%2,%3};\n"
        : "+f"(c[0]), "+f"(c[1]), "+f"(c[2]), "+f"(c[3])
        : "r"(__float_as_uint(a[0])), "r"(__float_as_uint(a[1])),
          "r"(__float_as_uint(a[2])), "r"(__float_as_uint(a[3])),
          "r"(__float_as_uint(b[0])), "r"(__float_as_uint(b[1])));
}

// ---------------------------------------------------------------------------
// Projection GEMM (tf32 tensor cores): C[8192,128] = A[8192,1024]@W[1024,128]+b
// grid (64, 3), 256 threads = 8 warps (4 m x 2 n). Tile 128x128, BK=32.
// Register-staged prefetch of the next chunk overlaps LDG with MMA.
// As[m][k] pitch 36, Ws[k][n] pitch 136 -> conflict-free fragment reads.
// ---------------------------------------------------------------------------
#define PA_PITCH 36
#define PW_PITCH 136

__global__ __launch_bounds__(256) void proj_kernel(
    const float* __restrict__ x, const float* __restrict__ y,
    const float* __restrict__ Wq, const float* __restrict__ bq,
    const float* __restrict__ Wk, const float* __restrict__ bk,
    const float* __restrict__ Wv, const float* __restrict__ bv)
{
    const float* A; const float* W; const float* bias; float* C;
    if (blockIdx.y == 0)      { A = x; W = Wq; bias = bq; C = g_q; }
    else if (blockIdx.y == 1) { A = y; W = Wk; bias = bk; C = g_k; }
    else                      { A = y; W = Wv; bias = bv; C = g_v; }

    __shared__ float As[128 * PA_PITCH];   // [m][k], BK=32 cols used
    __shared__ float Ws[32 * PW_PITCH];    // [k][n]

    const int tid  = threadIdx.x;
    const int wid  = tid >> 5;
    const int lane = tid & 31;
    const int lr = lane >> 2, lc = lane & 3;
    const int rw = (wid & 3) * 32;   // warp row base within tile
    const int cw = (wid >> 2) * 64;  // warp col base within tile
    const int row0 = blockIdx.x * 128;

    // load indices (4 float4 each for A and W per chunk)
    // A: 128 rows x 8 float4 along k ; W: 32 k-rows x 32 float4 along n
    float4 rA[4], rW[4];
    #pragma unroll
    for (int i = 0; i < 4; i++) {
        const int g = tid + i * 256;
        rA[i] = *(const float4*)(A + (size_t)(row0 + (g >> 3)) * XS_ + (g & 7) * 4);
        rW[i] = *(const float4*)(W + (size_t)(g >> 5) * PD_ + (g & 31) * 4);
    }

    float acc[2][8][4];
    #pragma unroll
    for (int mf = 0; mf < 2; mf++)
        #pragma unroll
        for (int nf = 0; nf < 8; nf++)
            #pragma unroll
            for (int r = 0; r < 4; r++) acc[mf][nf][r] = 0.0f;

    for (int c = 0; c < 32; c++) {
        __syncthreads();
        #pragma unroll
        for (int i = 0; i < 4; i++) {
            const int g = tid + i * 256;
            const int ar = g >> 3, ak = (g & 7) * 4;
            As[ar * PA_PITCH + ak + 0] = to_tf32(rA[i].x);
            As[ar * PA_PITCH + ak + 1] = to_tf32(rA[i].y);
            As[ar * PA_PITCH + ak + 2] = to_tf32(rA[i].z);
            As[ar * PA_PITCH + ak + 3] = to_tf32(rA[i].w);
            const int wk = g >> 5, wn = (g & 31) * 4;
            Ws[wk * PW_PITCH + wn + 0] = to_tf32(rW[i].x);
            Ws[wk * PW_PITCH + wn + 1] = to_tf32(rW[i].y);
            Ws[wk * PW_PITCH + wn + 2] = to_tf32(rW[i].z);
            Ws[wk * PW_PITCH + wn + 3] = to_tf32(rW[i].w);
        }
        __syncthreads();

        if (c < 31) {
            const int k0 = (c + 1) * 32;
            #pragma unroll
            for (int i = 0; i < 4; i++) {
                const int g = tid + i * 256;
                rA[i] = *(const float4*)(A + (size_t)(row0 + (g >> 3)) * XS_ + k0 + (g & 7) * 4);
                rW[i] = *(const float4*)(W + (size_t)(k0 + (g >> 5)) * PD_ + (g & 31) * 4);
            }
        }

        #pragma unroll
        for (int kf = 0; kf < 4; kf++) {
            const int k = kf * 8;
            float a[2][4];
            #pragma unroll
            for (int mf = 0; mf < 2; mf++) {
                const int r = rw + mf * 16 + lr;
                a[mf][0] = As[r * PA_PITCH + k + lc];
                a[mf][1] = As[(r + 8) * PA_PITCH + k + lc];
                a[mf][2] = As[r * PA_PITCH + k + lc + 4];
                a[mf][3] = As[(r + 8) * PA_PITCH + k + lc + 4];
            }
            #pragma unroll
            for (int nf = 0; nf < 8; nf++) {
                float b[2];
                const int col = cw + nf * 8 + lr;
                b[0] = Ws[(k + lc) * PW_PITCH + col];
                b[1] = Ws[(k + lc + 4) * PW_PITCH + col];
                mma_tf32(acc[0][nf], a[0], b);
                mma_tf32(acc[1][nf], a[1], b);
            }
        }
    }

    // Epilogue: +bias, round to tf32, store
    #pragma unroll
    for (int mf = 0; mf < 2; mf++) {
        #pragma unroll
        for (int nf = 0; nf < 8; nf++) {
            const int row = row0 + rw + mf * 16 + lr;
            const int col = cw + nf * 8 + 2 * lc;
            const float2 bb = *(const float2*)(bias + col);
            float2 o0, o1;
            o0.x = to_tf32(acc[mf][nf][0] + bb.x);
            o0.y = to_tf32(acc[mf][nf][1] + bb.y);
            o1.x = to_tf32(acc[mf][nf][2] + bb.x);
            o1.y = to_tf32(acc[mf][nf][3] + bb.y);
            *(float2*)(C + (size_t)row * PD_ + col) = o0;
            *(float2*)(C + (size_t)(row + 8) * PD_ + col) = o1;
        }
    }
}

// ---------------------------------------------------------------------------
// Flash attention, tf32 mma, post-softmax triu(k=1) mask.
// grid (32, 4), 128 threads = 4 warps; each warp owns 16 full S-rows.
// cp.async double-buffered K/V tiles (values pre-rounded to tf32 by proj).
// smem pitches: Qs/Ks 132, Vs 136, Ps 68 -> conflict-free fragment reads.
// ---------------------------------------------------------------------------
#define BQ  64
#define BKT 64
#define QP  132
#define VP  136
#define PP  68
#define SMF_Q  0
#define SMF_K  (64 * QP)                       // 2 buffers of 64*132
#define SMF_V  (SMF_K + 2 * 64 * QP)           // 2 buffers of 64*136
#define SMF_P  (SMF_V + 2 * 64 * VP)
#define SMEM_FLOATS (SMF_P + 64 * PP)
#define SMEM_BYTES  (SMEM_FLOATS * 4)

__global__ __launch_bounds__(128) void attn_kernel(const int* __restrict__ maskp,
                                                   float* __restrict__ out)
{
    extern __shared__ float sm[];
    float* Qs = sm + SMF_Q;   // [r][d] pitch 132
    float* Ks = sm + SMF_K;   // buf*[j][d] pitch 132
    float* Vs = sm + SMF_V;   // buf*[j][d] pitch 136
    float* Ps = sm + SMF_P;   // [r][j] pitch 68

    const int b = blockIdx.y;
    const int qbase = blockIdx.x * BQ;
    const float* Qg = g_q + ((size_t)b * LQ_ + qbase) * PD_;
    const float* Kg = g_k + (size_t)b * LK_ * PD_;
    const float* Vg = g_v + (size_t)b * LK_ * PD_;

    const int tid  = threadIdx.x;
    const int wid  = tid >> 5;
    const int lane = tid & 31;
    const int lr = lane >> 2, lc = lane & 3;
    const int r0w = wid * 16;              // warp's S-row base
    const int msk = *maskp;
    const float SCALE = 0.0883883476483184f;  // 1/sqrt(128)

    // Prologue: async-copy Q + K/V tile 0 (one commit group)
    #pragma unroll
    for (int i = 0; i < 16; i++) {
        const int g = tid + i * 128;       // 2048 float4 per tile
        const int j = g >> 5, d4 = (g & 31) * 4;
        __pipeline_memcpy_async(&Qs[j * QP + d4], Qg + (size_t)j * PD_ + d4, 16);
        __pipeline_memcpy_async(&Ks[j * QP + d4], Kg + (size_t)j * PD_ + d4, 16);
        __pipeline_memcpy_async(&Vs[j * VP + d4], Vg + (size_t)j * PD_ + d4, 16);
    }
    __pipeline_commit();

    float oacc[16][4];
    #pragma unroll
    for (int nf = 0; nf < 16; nf++)
        #pragma unroll
        for (int r = 0; r < 4; r++) oacc[nf][r] = 0.0f;
    float m_run[2] = {-1e30f, -1e30f};
    float l_run[2] = {0.0f, 0.0f};

    for (int t = 0; t < LK_ / BKT; t++) {
        const int kbase = t * BKT;
        const int buf = t & 1;
        float* Kb = Ks + buf * 64 * QP;
        float* Vb = Vs + buf * 64 * VP;

        __pipeline_wait_prior(0);
        __syncthreads();

        if (t + 1 < LK_ / BKT) {
            const int nb = (t + 1) & 1;
            float* Kn = Ks + nb * 64 * QP;
            float* Vn = Vs + nb * 64 * VP;
            const float* Kgs = Kg + (size_t)(kbase + BKT) * PD_;
            const float* Vgs = Vg + (size_t)(kbase + BKT) * PD_;
            #pragma unroll
            for (int i = 0; i < 16; i++) {
                const int g = tid + i * 128;
                const int j = g >> 5, d4 = (g & 31) * 4;
                __pipeline_memcpy_async(&Kn[j * QP + d4], Kgs + (size_t)j * PD_ + d4, 16);
                __pipeline_memcpy_async(&Vn[j * VP + d4], Vgs + (size_t)j * PD_ + d4, 16);
            }
            __pipeline_commit();
        }

        // ---- S = Q @ K^T (each warp: 16 rows x 64 cols) ----
        float sacc[8][4];
        #pragma unroll
        for (int nf = 0; nf < 8; nf++)
            #pragma unroll
            for (int r = 0; r < 4; r++) sacc[nf][r] = 0.0f;

        #pragma unroll 4
        for (int kf = 0; kf < 16; kf++) {
            const int k = kf * 8;
            float a[4];
            a[0] = Qs[(r0w + lr) * QP + k + lc];
            a[1] = Qs[(r0w + lr + 8) * QP + k + lc];
            a[2] = Qs[(r0w + lr) * QP + k + lc + 4];
            a[3] = Qs[(r0w + lr + 8) * QP + k + lc + 4];
            #pragma unroll
            for (int nf = 0; nf < 8; nf++) {
                float bfr[2];
                bfr[0] = Kb[(nf * 8 + lr) * QP + k + lc];
                bfr[1] = Kb[(nf * 8 + lr) * QP + k + lc + 4];
                mma_tf32(sacc[nf], a, bfr);
            }
        }

        // ---- online softmax (warp-local; rows lr and lr+8 of this warp) ----
        #pragma unroll
        for (int nf = 0; nf < 8; nf++)
            #pragma unroll
            for (int r = 0; r < 4; r++) sacc[nf][r] *= SCALE;

        float m_t[2] = {-1e30f, -1e30f};
        #pragma unroll
        for (int nf = 0; nf < 8; nf++) {
            m_t[0] = fmaxf(m_t[0], fmaxf(sacc[nf][0], sacc[nf][1]));
            m_t[1] = fmaxf(m_t[1], fmaxf(sacc[nf][2], sacc[nf][3]));
        }
        #pragma unroll
        for (int off = 2; off >= 1; off >>= 1) {
            m_t[0] = fmaxf(m_t[0], __shfl_xor_sync(0xffffffffu, m_t[0], off));
            m_t[1] = fmaxf(m_t[1], __shfl_xor_sync(0xffffffffu, m_t[1], off));
        }
        float m_new[2], corr[2], lp[2] = {0.0f, 0.0f};
        #pragma unroll
        for (int r = 0; r < 2; r++) {
            m_new[r] = fmaxf(m_run[r], m_t[r]);
            corr[r] = __expf(m_run[r] - m_new[r]);
        }
        #pragma unroll
        for (int nf = 0; nf < 8; nf++) {
            #pragma unroll
            for (int r = 0; r < 4; r++) {
                const float e = __expf(sacc[nf][r] - m_new[r >> 1]);
                sacc[nf][r] = e;
                lp[r >> 1] += e;
            }
        }
        #pragma unroll
        for (int off = 2; off >= 1; off >>= 1) {
            lp[0] += __shfl_xor_sync(0xffffffffu, lp[0], off);
            lp[1] += __shfl_xor_sync(0xffffffffu, lp[1], off);
        }
        #pragma unroll
        for (int r = 0; r < 2; r++) {
            l_run[r] = l_run[r] * corr[r] + lp[r];
            m_run[r] = m_new[r];
        }
        #pragma unroll
        for (int nf = 0; nf < 16; nf++) {
            oacc[nf][0] *= corr[0]; oacc[nf][1] *= corr[0];
            oacc[nf][2] *= corr[1]; oacc[nf][3] *= corr[1];
        }

        // Tile fully below/at diagonal for every row of this CTA -> P == 0
        const bool pv_skip = msk && (kbase + BKT - 1 <= qbase);
        if (!pv_skip) {
            // masked P -> smem (tf32-rounded)
            const int rowg0 = qbase + r0w + lr;
            const int rowg1 = rowg0 + 8;
            #pragma unroll
            for (int nf = 0; nf < 8; nf++) {
                const int col = nf * 8 + 2 * lc;
                const int kidx = kbase + col;
                const bool z00 = msk && (kidx     <= rowg0);
                const bool z01 = msk && (kidx + 1 <= rowg0);
                const bool z10 = msk && (kidx     <= rowg1);
                const bool z11 = msk && (kidx + 1 <= rowg1);
                Ps[(r0w + lr) * PP + col]     = z00 ? 0.0f : to_tf32(sacc[nf][0]);
                Ps[(r0w + lr) * PP + col + 1] = z01 ? 0.0f : to_tf32(sacc[nf][1]);
                Ps[(r0w + lr + 8) * PP + col]     = z10 ? 0.0f : to_tf32(sacc[nf][2]);
                Ps[(r0w + lr + 8) * PP + col + 1] = z11 ? 0.0f : to_tf32(sacc[nf][3]);
            }
            __syncwarp();

            // ---- O += P @ V ----
            #pragma unroll 2
            for (int jf = 0; jf < 8; jf++) {
                const int j = jf * 8;
                float a[4];
                a[0] = Ps[(r0w + lr) * PP + j + lc];
                a[1] = Ps[(r0w + lr + 8) * PP + j + lc];
                a[2] = Ps[(r0w + lr) * PP + j + lc + 4];
                a[3] = Ps[(r0w + lr + 8) * PP + j + lc + 4];
                #pragma unroll
                for (int nf = 0; nf < 16; nf++) {
                    float bfr[2];
                    bfr[0] = Vb[(j + lc) * VP + nf * 8 + lr];
                    bfr[1] = Vb[(j + lc + 4) * VP + nf * 8 + lr];
                    mma_tf32(oacc[nf], a, bfr);
                }
            }
            __syncwarp();
        }
    }

    // Epilogue: normalize by full denominator, store
    float* Og = out + ((size_t)b * LQ_ + qbase) * PD_;
    const float inv0 = 1.0f / l_run[0];
    const float inv1 = 1.0f / l_run[1];
    #pragma unroll
    for (int nf = 0; nf < 16; nf++) {
        const int row = r0w + lr;
        const int col = nf * 8 + 2 * lc;
        float2 o0 = make_float2(oacc[nf][0] * inv0, oacc[nf][1] * inv0);
        float2 o1 = make_float2(oacc[nf][2] * inv1, oacc[nf][3] * inv1);
        *(float2*)(Og + (size_t)row * PD_ + col) = o0;
        *(float2*)(Og + (size_t)(row + 8) * PD_ + col) = o1;
    }
}

// ---------------------------------------------------------------------------
extern "C" void kernel_launch(void* const* d_in, const int* in_sizes, int n_in,
                              void* d_out, int out_size)
{
    const float* x  = (const float*)d_in[0];
    const float* y  = (const float*)d_in[1];
    const float* Wq = (const float*)d_in[2];
    const float* bq = (const float*)d_in[3];
    const float* Wk = (const float*)d_in[4];
    const float* bk = (const float*)d_in[5];
    const float* Wv = (const float*)d_in[6];
    const float* bv = (const float*)d_in[7];
    const int* maskp = (const int*)d_in[8];
    float* out = (float*)d_out;

    (void)in_sizes; (void)n_in; (void)out_size;

    cudaFuncSetAttribute(attn_kernel,
                         cudaFuncAttributeMaxDynamicSharedMemorySize, SMEM_BYTES);

    dim3 pg(64, 3);
    proj_kernel<<<pg, 256>>>(x, y, Wq, bq, Wk, bk, Wv, bv);

    dim3 ag(LQ_ / BQ, B_);
    attn_kernel<<<ag, 128, SMEM_BYTES>>>(maskp, out);
}